// round 2
// baseline (speedup 1.0000x reference)
#include <cuda_runtime.h>
#include <math.h>
#include <float.h>

#define B   8
#define F   2048
#define NN  10000
#define J   10
#define R   20
#define H1  200
#define H2  100

#define FS   8            // F splits
#define FC   (F/FS)       // 256
#define TPB1 128
#define GROUPS (NN/4)     // 2500 float4 groups per (b)
#define NBLK ((GROUPS + TPB1 - 1)/TPB1)  // 20

// Scratch (device globals: no allocation allowed)
__device__ float g_part[(size_t)FS*B*J*NN];   // 25.6 MB partial emb sums, fits in L2
__device__ float g_mm[B*2*R*J];               // [8,400] minmax features

#define FMA2(acc, w, xv) asm("fma.rn.f32x2 %0, %1, %2, %0;" : "+l"(acc) : "l"(w), "l"(xv))

// ---------------------------------------------------------------------------
// Kernel 1: 1x1 conv partials.  emb_partial[fs][b][j][n] = sum_{f in chunk} x[b,f,n]*w[j,f]
// ---------------------------------------------------------------------------
__global__ __launch_bounds__(TPB1)
void conv_kernel(const float* __restrict__ x, const float* __restrict__ cw)
{
    __shared__ __align__(16) float2 ws[FC*J];   // (w,w) duplicated pairs, 20 KB

    const int b  = blockIdx.z;
    const int fs = blockIdx.y;
    const int f0 = fs * FC;

    for (int i = threadIdx.x; i < FC*J; i += TPB1) {
        int f = i / J, j = i - f*J;
        float w = cw[j*F + f0 + f];
        ws[i] = make_float2(w, w);
    }
    __syncthreads();

    int g = blockIdx.x * TPB1 + threadIdx.x;
    if (g >= GROUPS) return;
    int n = g * 4;

    const ulonglong2* xp = (const ulonglong2*)(x + ((size_t)b*F + f0)*NN + n);
    // stride between consecutive f rows: NN floats = 2500 ulonglong2
    unsigned long long acc0[J], acc1[J];
    #pragma unroll
    for (int j = 0; j < J; j++) { acc0[j] = 0ull; acc1[j] = 0ull; }

    #pragma unroll 2
    for (int f = 0; f < FC; f++) {
        ulonglong2 xv = __ldcs(xp);     // streaming: don't pollute L2 (keep it for g_part)
        xp += NN/4;
        const ulonglong2* wp = (const ulonglong2*)&ws[f*J];
        #pragma unroll
        for (int jj = 0; jj < 5; jj++) {
            ulonglong2 w2 = wp[jj];
            FMA2(acc0[2*jj  ], w2.x, xv.x);
            FMA2(acc1[2*jj  ], w2.x, xv.y);
            FMA2(acc0[2*jj+1], w2.y, xv.x);
            FMA2(acc1[2*jj+1], w2.y, xv.y);
        }
    }

    float* outp = g_part + ((size_t)fs*B + b)*J*NN + n;
    #pragma unroll
    for (int j = 0; j < J; j++) {
        float a, bb, c, d;
        asm("mov.b64 {%0,%1}, %2;" : "=f"(a), "=f"(bb) : "l"(acc0[j]));
        asm("mov.b64 {%0,%1}, %2;" : "=f"(c), "=f"(d)  : "l"(acc1[j]));
        *(float4*)(outp + (size_t)j*NN) = make_float4(a, bb, c, d);
    }
}

// ---------------------------------------------------------------------------
// Kernel 2: per-(b,j) top-20 / bottom-20 selection. One block per row.
// Row lives in registers (10 vals/thread); 20 rounds of simultaneous argmax+argmin.
// Winners marked NaN (NaN loses all comparisons -> excluded from both searches).
// ---------------------------------------------------------------------------
#define TPB2 1024
__global__ __launch_bounds__(TPB2)
void select_kernel(const float* __restrict__ cb)
{
    const int bj = blockIdx.x, b = bj / J, j = bj - b*J;
    const int tid = threadIdx.x;
    const int lane = tid & 31, wid = tid >> 5;

    float vals[10];
    #pragma unroll
    for (int k = 0; k < 10; k++) {
        int n = tid + k*TPB2;
        float s = __int_as_float(0x7fffffff);   // NaN pad
        if (n < NN) {
            s = 0.f;
            #pragma unroll
            for (int fs = 0; fs < FS; fs++)
                s += g_part[(((size_t)fs*B + b)*J + j)*NN + n];
        }
        vals[k] = s;
    }

    __shared__ float rv[32], rs[32];
    __shared__ int   ri[32], rj2[32];
    __shared__ int   s_mi, s_ni;

    const float bias = cb[j];
    float* out = g_mm + b*(2*R*J) + j*(2*R);

    for (int r = 0; r < R; r++) {
        float bv = -FLT_MAX; int bi = 0;
        float sv =  FLT_MAX; int si = 0;
        #pragma unroll
        for (int k = 0; k < 10; k++) {
            float v = vals[k]; int n = tid + k*TPB2;
            if (v > bv) { bv = v; bi = n; }
            if (v < sv) { sv = v; si = n; }
        }
        #pragma unroll
        for (int off = 16; off; off >>= 1) {
            float ov = __shfl_down_sync(0xffffffffu, bv, off);
            int   oi = __shfl_down_sync(0xffffffffu, bi, off);
            if (ov > bv || (ov == bv && oi < bi)) { bv = ov; bi = oi; }
            float pv = __shfl_down_sync(0xffffffffu, sv, off);
            int   pi = __shfl_down_sync(0xffffffffu, si, off);
            if (pv < sv || (pv == sv && pi < si)) { sv = pv; si = pi; }
        }
        if (lane == 0) { rv[wid] = bv; ri[wid] = bi; rs[wid] = sv; rj2[wid] = si; }
        __syncthreads();
        if (wid == 0) {
            bv = rv[lane]; bi = ri[lane]; sv = rs[lane]; si = rj2[lane];
            #pragma unroll
            for (int off = 16; off; off >>= 1) {
                float ov = __shfl_down_sync(0xffffffffu, bv, off);
                int   oi = __shfl_down_sync(0xffffffffu, bi, off);
                if (ov > bv || (ov == bv && oi < bi)) { bv = ov; bi = oi; }
                float pv = __shfl_down_sync(0xffffffffu, sv, off);
                int   pi = __shfl_down_sync(0xffffffffu, si, off);
                if (pv < sv || (pv == sv && pi < si)) { sv = pv; si = pi; }
            }
            if (lane == 0) {
                s_mi = bi; s_ni = si;
                out[r]           = bv + bias;   // top, descending
                out[2*R - 1 - r] = sv + bias;   // bottom, descending (r-th min -> slot 39-r)
            }
        }
        __syncthreads();
        int mi = s_mi, ni = s_ni;
        if ((mi & (TPB2-1)) == tid) {
            int kk = mi >> 10;
            #pragma unroll
            for (int k = 0; k < 10; k++) if (k == kk) vals[k] = __int_as_float(0x7fffffff);
        }
        if ((ni & (TPB2-1)) == tid) {
            int kk = ni >> 10;
            #pragma unroll
            for (int k = 0; k < 10; k++) if (k == kk) vals[k] = __int_as_float(0x7fffffff);
        }
        // rv/rs rewritten only after the next round's __syncthreads()
    }
}

// ---------------------------------------------------------------------------
// Kernel 3: tiny MLP 400 -> 200 -> 100 -> 2 (sigmoid, sigmoid, linear)
// ---------------------------------------------------------------------------
__global__ __launch_bounds__(512)
void mlp_kernel(const float* __restrict__ w1, const float* __restrict__ b1,
                const float* __restrict__ w2, const float* __restrict__ b2,
                const float* __restrict__ w3, const float* __restrict__ b3,
                float* __restrict__ out)
{
    __shared__ float sin_[B*2*R*J];   // 3200
    __shared__ float sh1[B*H1];       // 1600
    __shared__ float sh2[B*H2];       // 800
    const int tid = threadIdx.x;

    for (int i = tid; i < B*2*R*J; i += 512) sin_[i] = g_mm[i];
    __syncthreads();

    for (int o = tid; o < B*H1; o += 512) {
        int b = o / H1, k = o - b*H1;
        float s = b1[k];
        const float* inb = sin_ + b*(2*R*J);
        #pragma unroll 4
        for (int i = 0; i < 2*R*J; i++) s += inb[i] * w1[i*H1 + k];
        sh1[o] = 1.f / (1.f + expf(-s));
    }
    __syncthreads();

    for (int o = tid; o < B*H2; o += 512) {
        int b = o / H2, k = o - b*H2;
        float s = b2[k];
        const float* inb = sh1 + b*H1;
        #pragma unroll 4
        for (int i = 0; i < H1; i++) s += inb[i] * w2[i*H2 + k];
        sh2[o] = 1.f / (1.f + expf(-s));
    }
    __syncthreads();

    for (int o = tid; o < B*2; o += 512) {
        int b = o >> 1, k = o & 1;
        float s = b3[k];
        const float* inb = sh2 + b*H2;
        #pragma unroll 4
        for (int i = 0; i < H2; i++) s += inb[i] * w3[i*2 + k];
        out[o] = s;
    }
}

// ---------------------------------------------------------------------------
extern "C" void kernel_launch(void* const* d_in, const int* in_sizes, int n_in,
                              void* d_out, int out_size)
{
    const float* x  = (const float*)d_in[0];
    const float* cw = (const float*)d_in[1];
    const float* cb = (const float*)d_in[2];
    const float* w1 = (const float*)d_in[3];
    const float* b1 = (const float*)d_in[4];
    const float* w2 = (const float*)d_in[5];
    const float* b2 = (const float*)d_in[6];
    const float* w3 = (const float*)d_in[7];
    const float* b3 = (const float*)d_in[8];
    float* out = (float*)d_out;

    dim3 g1(NBLK, FS, B);
    conv_kernel<<<g1, TPB1>>>(x, cw);
    select_kernel<<<B*J, TPB2>>>(cb);
    mlp_kernel<<<1, 512>>>(w1, b1, w2, b2, w3, b3, out);
}

// round 3
// speedup vs baseline: 1.3779x; 1.3779x over previous
#include <cuda_runtime.h>
#include <math.h>
#include <float.h>

#define B   8
#define F   2048
#define NN  10000
#define J   10
#define R   20
#define H1  200
#define H2  100

#define FS   4            // F splits
#define FC   (F/FS)       // 512
#define TPB1 128
#define GROUPS (NN/4)     // 2500 float4 groups per (b)
#define NBLK ((GROUPS + TPB1 - 1)/TPB1)  // 20
#define UF   8            // f-loads batched per iteration (MLP depth)

// Scratch (device globals: no allocation allowed)
__device__ float g_part[(size_t)FS*B*J*NN];   // 12.8 MB partial emb sums, fits in L2
__device__ float g_mm[B*2*R*J];               // [8,400] minmax features

#define FMA2(acc, w, xv) asm("fma.rn.f32x2 %0, %1, %2, %0;" : "+l"(acc) : "l"(w), "l"(xv))

// ---------------------------------------------------------------------------
// Kernel 1: 1x1 conv partials.  g_part[fs][b][j][n] = sum_{f in chunk} x[b,f,n]*w[j,f]
// 8 LDG.128 batched up front per iteration -> MLP_eff ~8, hides DRAM latency.
// ---------------------------------------------------------------------------
__global__ __launch_bounds__(TPB1)
void conv_kernel(const float* __restrict__ x, const float* __restrict__ cw)
{
    __shared__ __align__(16) float2 ws[FC*J];   // (w,w) duplicated pairs, 40 KB

    const int b  = blockIdx.z;
    const int fs = blockIdx.y;
    const int f0 = fs * FC;

    for (int i = threadIdx.x; i < FC*J; i += TPB1) {
        int f = i / J, j = i - f*J;
        float w = cw[j*F + f0 + f];
        ws[i] = make_float2(w, w);
    }
    __syncthreads();

    int g = blockIdx.x * TPB1 + threadIdx.x;
    if (g >= GROUPS) return;
    int n = g * 4;

    const ulonglong2* xp = (const ulonglong2*)(x + ((size_t)b*F + f0)*NN + n);
    unsigned long long acc0[J], acc1[J];
    #pragma unroll
    for (int j = 0; j < J; j++) { acc0[j] = 0ull; acc1[j] = 0ull; }

    #pragma unroll 1
    for (int fb = 0; fb < FC; fb += UF) {
        ulonglong2 xv[UF];
        #pragma unroll
        for (int u = 0; u < UF; u++) {
            xv[u] = __ldcs(xp);          // streaming: keep L2 for g_part
            xp += NN/4;
        }
        #pragma unroll
        for (int u = 0; u < UF; u++) {
            const ulonglong2* wp = (const ulonglong2*)&ws[(fb + u)*J];
            #pragma unroll
            for (int jj = 0; jj < 5; jj++) {
                ulonglong2 w2 = wp[jj];
                FMA2(acc0[2*jj  ], w2.x, xv[u].x);
                FMA2(acc1[2*jj  ], w2.x, xv[u].y);
                FMA2(acc0[2*jj+1], w2.y, xv[u].x);
                FMA2(acc1[2*jj+1], w2.y, xv[u].y);
            }
        }
    }

    float* outp = g_part + ((size_t)fs*B + b)*J*NN + n;
    #pragma unroll
    for (int j = 0; j < J; j++) {
        float a, bb, c, d;
        asm("mov.b64 {%0,%1}, %2;" : "=f"(a), "=f"(bb) : "l"(acc0[j]));
        asm("mov.b64 {%0,%1}, %2;" : "=f"(c), "=f"(d)  : "l"(acc1[j]));
        *(float4*)(outp + (size_t)j*NN) = make_float4(a, bb, c, d);
    }
}

// ---------------------------------------------------------------------------
// Kernel 2: per-(b,j) top-20 / bottom-20 selection. One block per row.
// Row in registers (10 vals/thread); 20 rounds of simultaneous argmax+argmin.
// Winners marked NaN (NaN loses all comparisons). Also prefetches the MLP
// weights into L2 so kernel 3's reads are L2 hits.
// ---------------------------------------------------------------------------
#define TPB2 1024
__global__ __launch_bounds__(TPB2)
void select_kernel(const float* __restrict__ cb,
                   const float* __restrict__ w1, const float* __restrict__ w2,
                   const float* __restrict__ w3)
{
    const int bj = blockIdx.x, b = bj / J, j = bj - b*J;
    const int tid = threadIdx.x;
    const int lane = tid & 31, wid = tid >> 5;

    // Warm L2 with the MLP weights (free: overlapped with the partial reads).
    {
        int gid = bj * TPB2 + tid;                       // 0..81919
        if (gid < (2*R*J)*H1/32) {                       // w1: 80000 f -> 2500 lines
            const float* p = w1 + gid*32;
            asm volatile("prefetch.global.L2 [%0];" :: "l"(p));
        } else if (gid < (2*R*J)*H1/32 + H1*H2/32) {     // w2: 20000 f -> 625 lines
            const float* p = w2 + (gid - (2*R*J)*H1/32)*32;
            asm volatile("prefetch.global.L2 [%0];" :: "l"(p));
        } else if (gid < (2*R*J)*H1/32 + H1*H2/32 + 7) { // w3: 200 f -> 7 lines
            const float* p = w3 + (gid - (2*R*J)*H1/32 - H1*H2/32)*32;
            asm volatile("prefetch.global.L2 [%0];" :: "l"(p));
        }
    }

    float vals[10];
    #pragma unroll
    for (int k = 0; k < 10; k++) {
        int n = tid + k*TPB2;
        float s = __int_as_float(0x7fffffff);   // NaN pad
        if (n < NN) {
            s = 0.f;
            #pragma unroll
            for (int fs = 0; fs < FS; fs++)
                s += g_part[(((size_t)fs*B + b)*J + j)*NN + n];
        }
        vals[k] = s;
    }

    __shared__ float rv[32], rs[32];
    __shared__ int   ri[32], rj2[32];
    __shared__ int   s_mi, s_ni;

    const float bias = cb[j];
    float* out = g_mm + b*(2*R*J) + j*(2*R);

    for (int r = 0; r < R; r++) {
        float bv = -FLT_MAX; int bi = 0;
        float sv =  FLT_MAX; int si = 0;
        #pragma unroll
        for (int k = 0; k < 10; k++) {
            float v = vals[k]; int n = tid + k*TPB2;
            if (v > bv) { bv = v; bi = n; }
            if (v < sv) { sv = v; si = n; }
        }
        #pragma unroll
        for (int off = 16; off; off >>= 1) {
            float ov = __shfl_down_sync(0xffffffffu, bv, off);
            int   oi = __shfl_down_sync(0xffffffffu, bi, off);
            if (ov > bv || (ov == bv && oi < bi)) { bv = ov; bi = oi; }
            float pv = __shfl_down_sync(0xffffffffu, sv, off);
            int   pi = __shfl_down_sync(0xffffffffu, si, off);
            if (pv < sv || (pv == sv && pi < si)) { sv = pv; si = pi; }
        }
        if (lane == 0) { rv[wid] = bv; ri[wid] = bi; rs[wid] = sv; rj2[wid] = si; }
        __syncthreads();
        if (wid == 0) {
            bv = rv[lane]; bi = ri[lane]; sv = rs[lane]; si = rj2[lane];
            #pragma unroll
            for (int off = 16; off; off >>= 1) {
                float ov = __shfl_down_sync(0xffffffffu, bv, off);
                int   oi = __shfl_down_sync(0xffffffffu, bi, off);
                if (ov > bv || (ov == bv && oi < bi)) { bv = ov; bi = oi; }
                float pv = __shfl_down_sync(0xffffffffu, sv, off);
                int   pi = __shfl_down_sync(0xffffffffu, si, off);
                if (pv < sv || (pv == sv && pi < si)) { sv = pv; si = pi; }
            }
            if (lane == 0) {
                s_mi = bi; s_ni = si;
                out[r]           = bv + bias;   // top, descending
                out[2*R - 1 - r] = sv + bias;   // bottom, descending
            }
        }
        __syncthreads();
        int mi = s_mi, ni = s_ni;
        if ((mi & (TPB2-1)) == tid) {
            int kk = mi >> 10;
            #pragma unroll
            for (int k = 0; k < 10; k++) if (k == kk) vals[k] = __int_as_float(0x7fffffff);
        }
        if ((ni & (TPB2-1)) == tid) {
            int kk = ni >> 10;
            #pragma unroll
            for (int k = 0; k < 10; k++) if (k == kk) vals[k] = __int_as_float(0x7fffffff);
        }
    }
}

// ---------------------------------------------------------------------------
// Kernel 3: tiny MLP 400 -> 200 -> 100 -> 2. One block per batch element.
// Weights are L2-resident (prefetched by kernel 2); coalesced over output k.
// ---------------------------------------------------------------------------
__global__ __launch_bounds__(256)
void mlp_kernel(const float* __restrict__ w1, const float* __restrict__ b1,
                const float* __restrict__ w2, const float* __restrict__ b2,
                const float* __restrict__ w3, const float* __restrict__ b3,
                float* __restrict__ out)
{
    __shared__ float sin_[2*R*J];   // 400
    __shared__ float sh1[H1];       // 200
    __shared__ float sh2[H2];       // 100
    const int b = blockIdx.x;
    const int tid = threadIdx.x;

    for (int i = tid; i < 2*R*J; i += 256) sin_[i] = g_mm[b*(2*R*J) + i];
    __syncthreads();

    if (tid < H1) {
        float s = b1[tid];
        #pragma unroll 8
        for (int i = 0; i < 2*R*J; i++) s += sin_[i] * w1[i*H1 + tid];
        sh1[tid] = 1.f / (1.f + expf(-s));
    }
    __syncthreads();

    if (tid < H2) {
        float s = b2[tid];
        #pragma unroll 8
        for (int i = 0; i < H1; i++) s += sh1[i] * w2[i*H2 + tid];
        sh2[tid] = 1.f / (1.f + expf(-s));
    }
    __syncthreads();

    if (tid < 64) {
        int k = tid >> 5, lane = tid & 31;
        float s = 0.f;
        #pragma unroll
        for (int i = lane; i < H2; i += 32) s += sh2[i] * w3[i*2 + k];
        #pragma unroll
        for (int off = 16; off; off >>= 1) s += __shfl_down_sync(0xffffffffu, s, off);
        if (lane == 0) out[b*2 + k] = s + b3[k];
    }
}

// ---------------------------------------------------------------------------
extern "C" void kernel_launch(void* const* d_in, const int* in_sizes, int n_in,
                              void* d_out, int out_size)
{
    const float* x  = (const float*)d_in[0];
    const float* cw = (const float*)d_in[1];
    const float* cb = (const float*)d_in[2];
    const float* w1 = (const float*)d_in[3];
    const float* b1 = (const float*)d_in[4];
    const float* w2 = (const float*)d_in[5];
    const float* b2 = (const float*)d_in[6];
    const float* w3 = (const float*)d_in[7];
    const float* b3 = (const float*)d_in[8];
    float* out = (float*)d_out;

    dim3 g1(NBLK, FS, B);
    conv_kernel<<<g1, TPB1>>>(x, cw);
    select_kernel<<<B*J, TPB2>>>(cb, w1, w2, w3);
    mlp_kernel<<<B, 256>>>(w1, b1, w2, b2, w3, b3, out);
}

// round 4
// speedup vs baseline: 1.5184x; 1.1019x over previous
#include <cuda_runtime.h>
#include <math.h>
#include <float.h>

#define B   8
#define F   2048
#define NN  10000
#define J   10
#define R   20
#define H1  200
#define H2  100

#define FS   4            // F splits
#define FC   (F/FS)       // 512
#define TPB1 128
#define GROUPS (NN/4)     // 2500 float4 groups per (b)
#define NBLK ((GROUPS + TPB1 - 1)/TPB1)  // 20
#define UF   4            // pipeline half-depth (double buffered)
#define SROW (NN/4)       // x row stride in ulonglong2 units (2500)

// Scratch (device globals: no allocation allowed)
__device__ float g_part[(size_t)FS*B*J*NN];   // 12.8 MB partial emb sums (L2-resident)
__device__ float g_mm[B*2*R*J];               // [8,400] minmax features

#define FMA2(acc, w, xv) asm("fma.rn.f32x2 %0, %1, %2, %0;" : "+l"(acc) : "l"(w), "l"(xv))

// ---------------------------------------------------------------------------
// Kernel 1: 1x1 conv partials, software-pipelined (double-buffered loads).
// g_part[fs][b][j][n] = sum_{f in chunk} x[b,f,n]*w[j,f]
// ---------------------------------------------------------------------------
__device__ __forceinline__ void conv_fma(unsigned long long* acc0, unsigned long long* acc1,
                                         const ulonglong2* buf, const float2* ws, int fbase)
{
    #pragma unroll
    for (int u = 0; u < UF; u++) {
        const ulonglong2* wp = (const ulonglong2*)&ws[(fbase + u)*J];
        ulonglong2 xv = buf[u];
        #pragma unroll
        for (int jj = 0; jj < 5; jj++) {
            ulonglong2 w2 = wp[jj];
            FMA2(acc0[2*jj  ], w2.x, xv.x);
            FMA2(acc1[2*jj  ], w2.x, xv.y);
            FMA2(acc0[2*jj+1], w2.y, xv.x);
            FMA2(acc1[2*jj+1], w2.y, xv.y);
        }
    }
}

__global__ __launch_bounds__(TPB1, 5)
void conv_kernel(const float* __restrict__ x, const float* __restrict__ cw)
{
    __shared__ __align__(16) float2 ws[FC*J];   // (w,w) duplicated pairs, 40 KB

    const int b  = blockIdx.z;
    const int fs = blockIdx.y;
    const int f0 = fs * FC;

    for (int i = threadIdx.x; i < FC*J; i += TPB1) {
        int f = i / J, j = i - f*J;
        float w = cw[j*F + f0 + f];
        ws[i] = make_float2(w, w);
    }
    __syncthreads();

    int g = blockIdx.x * TPB1 + threadIdx.x;
    if (g >= GROUPS) return;
    int n = g * 4;

    const ulonglong2* xp = (const ulonglong2*)(x + ((size_t)b*F + f0)*NN + n);

    unsigned long long acc0[J], acc1[J];
    #pragma unroll
    for (int j = 0; j < J; j++) { acc0[j] = 0ull; acc1[j] = 0ull; }

    ulonglong2 bufA[UF], bufB[UF];

    // prologue: rows 0..UF-1
    #pragma unroll
    for (int u = 0; u < UF; u++) bufA[u] = __ldcs(xp + (size_t)u*SROW);

    #pragma unroll 1
    for (int fb = 0; fb < FC; fb += 2*UF) {
        // loads for second half of this block (rows fb+UF .. fb+2UF-1)
        const ulonglong2* p1 = xp + (size_t)(fb + UF)*SROW;
        #pragma unroll
        for (int u = 0; u < UF; u++) bufB[u] = __ldcs(p1 + (size_t)u*SROW);

        conv_fma(acc0, acc1, bufA, ws, fb);

        // loads for next block's first half (clamped on last iter; values discarded)
        int nf = (fb + 2*UF < FC) ? (fb + 2*UF) : 0;
        const ulonglong2* p2 = xp + (size_t)nf*SROW;
        #pragma unroll
        for (int u = 0; u < UF; u++) bufA[u] = __ldcs(p2 + (size_t)u*SROW);

        conv_fma(acc0, acc1, bufB, ws, fb + UF);
    }

    float* outp = g_part + ((size_t)fs*B + b)*J*NN + n;
    #pragma unroll
    for (int j = 0; j < J; j++) {
        float a, bb, c, d;
        asm("mov.b64 {%0,%1}, %2;" : "=f"(a), "=f"(bb) : "l"(acc0[j]));
        asm("mov.b64 {%0,%1}, %2;" : "=f"(c), "=f"(d)  : "l"(acc1[j]));
        *(float4*)(outp + (size_t)j*NN) = make_float4(a, bb, c, d);
    }
}

// ---------------------------------------------------------------------------
// Kernel 2: per-(b,j) top-20 / bottom-20, sort-then-merge.
//   Phase 0: each thread sums its 10 values and sorts them descending (network).
//   Phase A: each warp merges its 32 sorted lists -> warp top-20 & bottom-20
//            (shfl-xor reductions, no block syncs).
//   Phase B: warp0 merges 32 warp-top lists, warp1 merges 32 warp-bottom lists.
// Also prefetches the MLP weights into L2.
// ---------------------------------------------------------------------------
#define TPB2 1024
#define NLAST (NN - 9*TPB2)   // 784: threads < NLAST have 10 values, else 9
#define LSTRIDE 13            // padded per-thread list stride (conflict-free-ish)

__global__ __launch_bounds__(TPB2)
void select_kernel(const float* __restrict__ cb,
                   const float* __restrict__ w1, const float* __restrict__ w2,
                   const float* __restrict__ w3)
{
    __shared__ float s[TPB2*LSTRIDE];       // 52 KB per-thread sorted lists + sentinels
    __shared__ float wt[32][21], wb[32][21];

    const int bj = blockIdx.x, b = bj / J, j = bj - b*J;
    const int tid = threadIdx.x;
    const int lane = tid & 31, wid = tid >> 5;
    const unsigned FULL = 0xffffffffu;

    // Warm L2 with the MLP weights (overlapped with the partial reads).
    {
        int gid = bj * TPB2 + tid;
        if (gid < (2*R*J)*H1/32) {
            asm volatile("prefetch.global.L2 [%0];" :: "l"(w1 + gid*32));
        } else if (gid < (2*R*J)*H1/32 + H1*H2/32) {
            asm volatile("prefetch.global.L2 [%0];" :: "l"(w2 + (gid - (2*R*J)*H1/32)*32));
        } else if (gid < (2*R*J)*H1/32 + H1*H2/32 + 7) {
            asm volatile("prefetch.global.L2 [%0];" :: "l"(w3 + (gid - (2*R*J)*H1/32 - H1*H2/32)*32));
        }
    }

    const float* p0 = g_part + (((size_t)0*B + b)*J + j)*NN;
    const float* p1 = g_part + (((size_t)1*B + b)*J + j)*NN;
    const float* p2 = g_part + (((size_t)2*B + b)*J + j)*NN;
    const float* p3 = g_part + (((size_t)3*B + b)*J + j)*NN;

    float v[10];
    #pragma unroll
    for (int k = 0; k < 10; k++) {
        int n = tid + k*TPB2;
        float sum = -FLT_MAX;                 // pad: sinks to tail of descending sort
        if (n < NN) sum = (p0[n] + p1[n]) + (p2[n] + p3[n]);
        v[k] = sum;
    }
    const int c = (tid < NLAST) ? 10 : 9;     // count of real values

    // Odd-even transposition sort, descending (10 passes -> guaranteed sorted).
    #pragma unroll
    for (int pass = 0; pass < 10; pass++) {
        #pragma unroll
        for (int i = (pass & 1); i + 1 < 10; i += 2) {
            float hi = fmaxf(v[i], v[i+1]);
            float lo = fminf(v[i], v[i+1]);
            v[i] = hi; v[i+1] = lo;
        }
    }

    float* my = s + tid*LSTRIDE;
    my[0] = FLT_MAX;                          // min-merge sentinel (never wins min)
    #pragma unroll
    for (int k = 0; k < 10; k++) my[1+k] = v[k];
    my[11] = -FLT_MAX;                        // max-merge sentinel (c=10 case)
    __syncwarp();

    // Phase A: warp-local merges. hv walks heads (max), lv walks tails (min).
    {
        int mp = 1, np = c;
        float hv = my[1];
        float lv = my[np];
        #pragma unroll 1
        for (int r = 0; r < R; r++) {
            float bv = hv;
            #pragma unroll
            for (int off = 16; off; off >>= 1)
                bv = fmaxf(bv, __shfl_xor_sync(FULL, bv, off));
            unsigned m = __ballot_sync(FULL, hv == bv);
            if (lane == __ffs(m) - 1) { mp++; hv = my[mp]; }
            if (lane == 0) wt[wid][r] = bv;

            float sv = lv;
            #pragma unroll
            for (int off = 16; off; off >>= 1)
                sv = fminf(sv, __shfl_xor_sync(FULL, sv, off));
            unsigned m2 = __ballot_sync(FULL, lv == sv);
            if (lane == __ffs(m2) - 1) { np--; lv = my[np]; }
            if (lane == 0) wb[wid][r] = sv;   // ascending (r-th smallest)
        }
        if (lane == 0) { wt[wid][20] = -FLT_MAX; wb[wid][20] = FLT_MAX; }
    }
    __syncthreads();

    // Phase B: two warps merge the 32 warp lists.
    const float bias = cb[j];
    float* out = g_mm + b*(2*R*J) + j*(2*R);

    if (wid == 0) {          // top-20, descending
        int p = 0; float hv = wt[lane][0];
        #pragma unroll 1
        for (int r = 0; r < R; r++) {
            float bv = hv;
            #pragma unroll
            for (int off = 16; off; off >>= 1)
                bv = fmaxf(bv, __shfl_xor_sync(FULL, bv, off));
            unsigned m = __ballot_sync(FULL, hv == bv);
            if (lane == __ffs(m) - 1) { p++; hv = wt[lane][p]; }
            if (lane == 0) out[r] = bv + bias;
        }
    } else if (wid == 1) {   // bottom-20: r-th smallest -> slot 39-r (descending block)
        int p = 0; float lv = wb[lane][0];
        #pragma unroll 1
        for (int r = 0; r < R; r++) {
            float sv = lv;
            #pragma unroll
            for (int off = 16; off; off >>= 1)
                sv = fminf(sv, __shfl_xor_sync(FULL, sv, off));
            unsigned m = __ballot_sync(FULL, lv == sv);
            if (lane == __ffs(m) - 1) { p++; lv = wb[lane][p]; }
            if (lane == 0) out[2*R - 1 - r] = sv + bias;
        }
    }
}

// ---------------------------------------------------------------------------
// Kernel 3: tiny MLP 400 -> 200 -> 100 -> 2. One block per batch element.
// Weights are L2-resident (prefetched by kernel 2).
// ---------------------------------------------------------------------------
__global__ __launch_bounds__(256)
void mlp_kernel(const float* __restrict__ w1, const float* __restrict__ b1,
                const float* __restrict__ w2, const float* __restrict__ b2,
                const float* __restrict__ w3, const float* __restrict__ b3,
                float* __restrict__ out)
{
    __shared__ float sin_[2*R*J];   // 400
    __shared__ float sh1[H1];       // 200
    __shared__ float sh2[H2];       // 100
    const int b = blockIdx.x;
    const int tid = threadIdx.x;

    for (int i = tid; i < 2*R*J; i += 256) sin_[i] = g_mm[b*(2*R*J) + i];
    __syncthreads();

    if (tid < H1) {
        float s = b1[tid];
        #pragma unroll 8
        for (int i = 0; i < 2*R*J; i++) s += sin_[i] * w1[i*H1 + tid];
        sh1[tid] = 1.f / (1.f + expf(-s));
    }
    __syncthreads();

    if (tid < H2) {
        float s = b2[tid];
        #pragma unroll 8
        for (int i = 0; i < H1; i++) s += sh1[i] * w2[i*H2 + tid];
        sh2[tid] = 1.f / (1.f + expf(-s));
    }
    __syncthreads();

    if (tid < 64) {
        int k = tid >> 5, lane = tid & 31;
        float s = 0.f;
        #pragma unroll
        for (int i = lane; i < H2; i += 32) s += sh2[i] * w3[i*2 + k];
        #pragma unroll
        for (int off = 16; off; off >>= 1) s += __shfl_down_sync(0xffffffffu, s, off);
        if (lane == 0) out[b*2 + k] = s + b3[k];
    }
}

// ---------------------------------------------------------------------------
extern "C" void kernel_launch(void* const* d_in, const int* in_sizes, int n_in,
                              void* d_out, int out_size)
{
    const float* x  = (const float*)d_in[0];
    const float* cw = (const float*)d_in[1];
    const float* cb = (const float*)d_in[2];
    const float* w1 = (const float*)d_in[3];
    const float* b1 = (const float*)d_in[4];
    const float* w2 = (const float*)d_in[5];
    const float* b2 = (const float*)d_in[6];
    const float* w3 = (const float*)d_in[7];
    const float* b3 = (const float*)d_in[8];
    float* out = (float*)d_out;

    dim3 g1(NBLK, FS, B);
    conv_kernel<<<g1, TPB1>>>(x, cw);
    select_kernel<<<B*J, TPB2>>>(cb, w1, w2, w3);
    mlp_kernel<<<B, 256>>>(w1, b1, w2, b2, w3, b3, out);
}

// round 5
// speedup vs baseline: 1.5353x; 1.0111x over previous
#include <cuda_runtime.h>
#include <math.h>
#include <float.h>

#define B   8
#define F   2048
#define NN  10000
#define J   10
#define R   20
#define H1  200
#define H2  100

#define FS   4            // F splits
#define FC   (F/FS)       // 512
#define TPB1 128
#define GROUPS (NN/4)     // 2500 float4 groups per (b)
#define NBLK ((GROUPS + TPB1 - 1)/TPB1)  // 20
#define UF   4            // pipeline half-depth (double buffered)
#define SROW (NN/4)       // x row stride in ulonglong2 units (2500)

// Scratch (device globals: no allocation allowed)
__device__ float g_part[(size_t)FS*B*J*NN];   // 12.8 MB partial emb sums (L2-resident)
__device__ float g_mm[B*2*R*J];               // [8,400] minmax features

#define FMA2(acc, w, xv) asm("fma.rn.f32x2 %0, %1, %2, %0;" : "+l"(acc) : "l"(w), "l"(xv))

// ---------------------------------------------------------------------------
// Kernel 1: 1x1 conv partials, software-pipelined + warp-lockstep loads.
// The two __syncthreads per iteration keep all 4 warps issuing their load
// quartets together, so each touched DRAM row serves 2KB (whole block) per
// activation instead of 512B (one drifted warp).
// ---------------------------------------------------------------------------
__device__ __forceinline__ void conv_fma(unsigned long long* acc0, unsigned long long* acc1,
                                         const ulonglong2* buf, const float2* ws, int fbase)
{
    #pragma unroll
    for (int u = 0; u < UF; u++) {
        const ulonglong2* wp = (const ulonglong2*)&ws[(fbase + u)*J];
        ulonglong2 xv = buf[u];
        #pragma unroll
        for (int jj = 0; jj < 5; jj++) {
            ulonglong2 w2 = wp[jj];
            FMA2(acc0[2*jj  ], w2.x, xv.x);
            FMA2(acc1[2*jj  ], w2.x, xv.y);
            FMA2(acc0[2*jj+1], w2.y, xv.x);
            FMA2(acc1[2*jj+1], w2.y, xv.y);
        }
    }
}

__global__ __launch_bounds__(TPB1, 5)
void conv_kernel(const float* __restrict__ x, const float* __restrict__ cw)
{
    __shared__ __align__(16) float2 ws[FC*J];   // (w,w) duplicated pairs, 40 KB

    const int b  = blockIdx.z;
    const int fs = blockIdx.y;
    const int f0 = fs * FC;

    for (int i = threadIdx.x; i < FC*J; i += TPB1) {
        int f = i / J, j = i - f*J;
        float w = cw[j*F + f0 + f];
        ws[i] = make_float2(w, w);
    }
    __syncthreads();

    int g = blockIdx.x * TPB1 + threadIdx.x;
    if (g >= GROUPS) return;    // exited threads don't participate in bar.sync (sm_70+)
    int n = g * 4;

    const ulonglong2* xp = (const ulonglong2*)(x + ((size_t)b*F + f0)*NN + n);

    unsigned long long acc0[J], acc1[J];
    #pragma unroll
    for (int j = 0; j < J; j++) { acc0[j] = 0ull; acc1[j] = 0ull; }

    ulonglong2 bufA[UF], bufB[UF];

    // prologue: rows 0..UF-1
    #pragma unroll
    for (int u = 0; u < UF; u++) bufA[u] = __ldcs(xp + (size_t)u*SROW);

    #pragma unroll 1
    for (int fb = 0; fb < FC; fb += 2*UF) {
        __syncthreads();        // re-align warps: load quartets hit rows together
        const ulonglong2* p1 = xp + (size_t)(fb + UF)*SROW;
        #pragma unroll
        for (int u = 0; u < UF; u++) bufB[u] = __ldcs(p1 + (size_t)u*SROW);

        conv_fma(acc0, acc1, bufA, ws, fb);

        __syncthreads();
        int nf = (fb + 2*UF < FC) ? (fb + 2*UF) : 0;   // clamped; values discarded
        const ulonglong2* p2 = xp + (size_t)nf*SROW;
        #pragma unroll
        for (int u = 0; u < UF; u++) bufA[u] = __ldcs(p2 + (size_t)u*SROW);

        conv_fma(acc0, acc1, bufB, ws, fb + UF);
    }

    float* outp = g_part + ((size_t)fs*B + b)*J*NN + n;
    #pragma unroll
    for (int j = 0; j < J; j++) {
        float a, bb, c, d;
        asm("mov.b64 {%0,%1}, %2;" : "=f"(a), "=f"(bb) : "l"(acc0[j]));
        asm("mov.b64 {%0,%1}, %2;" : "=f"(c), "=f"(d)  : "l"(acc1[j]));
        *(float4*)(outp + (size_t)j*NN) = make_float4(a, bb, c, d);
    }
}

// ---------------------------------------------------------------------------
// Kernel 2: per-(b,j) top-20 / bottom-20, sort-then-merge, float4 loads.
//   Phase 0: each thread sums up to 3 float4 groups (12 vals) and sorts them
//            descending (odd-even network; -FLT_MAX pads sink to the tail).
//   Phase A: warp-local 20-round head(max)/tail(min) merges (shfl, no syncs).
//   Phase B: warp0 merges 32 warp-top lists, warp1 the 32 warp-bottom lists.
// Also prefetches the MLP weights into L2.
// ---------------------------------------------------------------------------
#define TPB2 1024
#define LSTRIDE 14            // sentinel + 12 vals + tail sentinel

__global__ __launch_bounds__(TPB2)
void select_kernel(const float* __restrict__ cb,
                   const float* __restrict__ w1, const float* __restrict__ w2,
                   const float* __restrict__ w3)
{
    __shared__ float s[TPB2*LSTRIDE];       // per-thread sorted lists (+sentinels)
    __shared__ float wt[32][21], wb[32][21];

    const int bj = blockIdx.x, b = bj / J, j = bj - b*J;
    const int tid = threadIdx.x;
    const int lane = tid & 31, wid = tid >> 5;
    const unsigned FULL = 0xffffffffu;

    // Warm L2 with the MLP weights (overlapped with the partial reads).
    {
        int gid = bj * TPB2 + tid;
        if (gid < (2*R*J)*H1/32) {
            asm volatile("prefetch.global.L2 [%0];" :: "l"(w1 + gid*32));
        } else if (gid < (2*R*J)*H1/32 + H1*H2/32) {
            asm volatile("prefetch.global.L2 [%0];" :: "l"(w2 + (gid - (2*R*J)*H1/32)*32));
        } else if (gid < (2*R*J)*H1/32 + H1*H2/32 + 7) {
            asm volatile("prefetch.global.L2 [%0];" :: "l"(w3 + (gid - (2*R*J)*H1/32 - H1*H2/32)*32));
        }
    }

    const float4* p0 = (const float4*)(g_part + (((size_t)0*B + b)*J + j)*NN);
    const float4* p1 = (const float4*)(g_part + (((size_t)1*B + b)*J + j)*NN);
    const float4* p2 = (const float4*)(g_part + (((size_t)2*B + b)*J + j)*NN);
    const float4* p3 = (const float4*)(g_part + (((size_t)3*B + b)*J + j)*NN);

    float v[12];
    #pragma unroll
    for (int k = 0; k < 12; k++) v[k] = -FLT_MAX;   // pads sink in descending sort
    int c = 0;                                       // real-value count
    #pragma unroll
    for (int k = 0; k < 3; k++) {
        int gidx = tid + k*TPB2;
        if (gidx < GROUPS) {
            float4 a = p0[gidx], bb = p1[gidx], cc = p2[gidx], dd = p3[gidx];
            v[4*k+0] = (a.x + bb.x) + (cc.x + dd.x);
            v[4*k+1] = (a.y + bb.y) + (cc.y + dd.y);
            v[4*k+2] = (a.z + bb.z) + (cc.z + dd.z);
            v[4*k+3] = (a.w + bb.w) + (cc.w + dd.w);
            c += 4;
        }
    }

    // Odd-even transposition sort, descending (12 passes -> sorted).
    #pragma unroll
    for (int pass = 0; pass < 12; pass++) {
        #pragma unroll
        for (int i = (pass & 1); i + 1 < 12; i += 2) {
            float hi = fmaxf(v[i], v[i+1]);
            float lo = fminf(v[i], v[i+1]);
            v[i] = hi; v[i+1] = lo;
        }
    }

    float* my = s + tid*LSTRIDE;
    my[0] = FLT_MAX;                          // min-walk sentinel
    #pragma unroll
    for (int k = 0; k < 12; k++) my[1+k] = v[k];
    my[13] = -FLT_MAX;                        // max-walk sentinel (c=12 case)
    __syncwarp();

    // Phase A: warp-local merges. hv walks heads (max), lv walks tails (min).
    {
        int mp = 1, np = c;                   // np=0 -> my[0]=+inf (never wins min)
        float hv = my[1];
        float lv = my[np];
        #pragma unroll 1
        for (int r = 0; r < R; r++) {
            float bv = hv;
            #pragma unroll
            for (int off = 16; off; off >>= 1)
                bv = fmaxf(bv, __shfl_xor_sync(FULL, bv, off));
            unsigned m = __ballot_sync(FULL, hv == bv);
            if (lane == __ffs(m) - 1) { mp++; hv = my[mp]; }
            if (lane == 0) wt[wid][r] = bv;

            float sv = lv;
            #pragma unroll
            for (int off = 16; off; off >>= 1)
                sv = fminf(sv, __shfl_xor_sync(FULL, sv, off));
            unsigned m2 = __ballot_sync(FULL, lv == sv);
            if (lane == __ffs(m2) - 1) { np--; lv = my[np]; }
            if (lane == 0) wb[wid][r] = sv;   // ascending (r-th smallest)
        }
        if (lane == 0) { wt[wid][20] = -FLT_MAX; wb[wid][20] = FLT_MAX; }
    }
    __syncthreads();

    // Phase B: two warps merge the 32 warp lists.
    const float bias = cb[j];
    float* out = g_mm + b*(2*R*J) + j*(2*R);

    if (wid == 0) {          // top-20, descending
        int p = 0; float hv = wt[lane][0];
        #pragma unroll 1
        for (int r = 0; r < R; r++) {
            float bv = hv;
            #pragma unroll
            for (int off = 16; off; off >>= 1)
                bv = fmaxf(bv, __shfl_xor_sync(FULL, bv, off));
            unsigned m = __ballot_sync(FULL, hv == bv);
            if (lane == __ffs(m) - 1) { p++; hv = wt[lane][p]; }
            if (lane == 0) out[r] = bv + bias;
        }
    } else if (wid == 1) {   // bottom-20: r-th smallest -> slot 39-r
        int p = 0; float lv = wb[lane][0];
        #pragma unroll 1
        for (int r = 0; r < R; r++) {
            float sv = lv;
            #pragma unroll
            for (int off = 16; off; off >>= 1)
                sv = fminf(sv, __shfl_xor_sync(FULL, sv, off));
            unsigned m = __ballot_sync(FULL, lv == sv);
            if (lane == __ffs(m) - 1) { p++; lv = wb[lane][p]; }
            if (lane == 0) out[2*R - 1 - r] = sv + bias;
        }
    }
}

// ---------------------------------------------------------------------------
// Kernel 3: tiny MLP 400 -> 200 -> 100 -> 2. One block per batch element.
// Weights are L2-resident (prefetched by kernel 2).
// ---------------------------------------------------------------------------
__global__ __launch_bounds__(256)
void mlp_kernel(const float* __restrict__ w1, const float* __restrict__ b1,
                const float* __restrict__ w2, const float* __restrict__ b2,
                const float* __restrict__ w3, const float* __restrict__ b3,
                float* __restrict__ out)
{
    __shared__ float sin_[2*R*J];   // 400
    __shared__ float sh1[H1];       // 200
    __shared__ float sh2[H2];       // 100
    const int b = blockIdx.x;
    const int tid = threadIdx.x;

    for (int i = tid; i < 2*R*J; i += 256) sin_[i] = g_mm[b*(2*R*J) + i];
    __syncthreads();

    if (tid < H1) {
        float s = b1[tid];
        #pragma unroll 8
        for (int i = 0; i < 2*R*J; i++) s += sin_[i] * w1[i*H1 + tid];
        sh1[tid] = 1.f / (1.f + expf(-s));
    }
    __syncthreads();

    if (tid < H2) {
        float s = b2[tid];
        #pragma unroll 8
        for (int i = 0; i < H1; i++) s += sh1[i] * w2[i*H2 + tid];
        sh2[tid] = 1.f / (1.f + expf(-s));
    }
    __syncthreads();

    if (tid < 64) {
        int k = tid >> 5, lane = tid & 31;
        float s = 0.f;
        #pragma unroll
        for (int i = lane; i < H2; i += 32) s += sh2[i] * w3[i*2 + k];
        #pragma unroll
        for (int off = 16; off; off >>= 1) s += __shfl_down_sync(0xffffffffu, s, off);
        if (lane == 0) out[b*2 + k] = s + b3[k];
    }
}

// ---------------------------------------------------------------------------
extern "C" void kernel_launch(void* const* d_in, const int* in_sizes, int n_in,
                              void* d_out, int out_size)
{
    const float* x  = (const float*)d_in[0];
    const float* cw = (const float*)d_in[1];
    const float* cb = (const float*)d_in[2];
    const float* w1 = (const float*)d_in[3];
    const float* b1 = (const float*)d_in[4];
    const float* w2 = (const float*)d_in[5];
    const float* b2 = (const float*)d_in[6];
    const float* w3 = (const float*)d_in[7];
    const float* b3 = (const float*)d_in[8];
    float* out = (float*)d_out;

    dim3 g1(NBLK, FS, B);
    conv_kernel<<<g1, TPB1>>>(x, cw);
    select_kernel<<<B*J, TPB2>>>(cb, w1, w2, w3);
    mlp_kernel<<<B, 256>>>(w1, b1, w2, b2, w3, b3, out);
}

// round 6
// speedup vs baseline: 1.5846x; 1.0321x over previous
#include <cuda_runtime.h>
#include <math.h>
#include <float.h>

#define B   8
#define F   2048
#define NN  10000
#define J   10
#define R   20
#define H1  200
#define H2  100

#define FS   8            // F splits
#define FC   (F/FS)       // 256 f-rows per block
#define TPB1 128
#define WINF 512          // floats per n-window (2KB)
#define NBLK1 ((NN + WINF - 1)/WINF)   // 20 (last window = 272 floats)
#define NST  4            // pipeline stages
#define CROWS 8           // f-rows per stage/chunk
#define NCHUNK (FC/CROWS) // 32

#define WS_BYTES    (FC*J*8)          // float2 dup weights: 20480
#define STAGE_BYTES (CROWS*WINF*4)    // 16384 per stage
#define SMEM_CONV   (WS_BYTES + NST*STAGE_BYTES + 64)

// Scratch (device globals: no allocation allowed)
__device__ float g_part[(size_t)FS*B*J*NN];   // 25.6 MB partial emb sums
__device__ float g_mm[B*2*R*J];               // [8,400] minmax features

#define FMA2(acc, w, xv) asm("fma.rn.f32x2 %0, %1, %2, %0;" : "+l"(acc) : "l"(w), "l"(xv))

__device__ __forceinline__ unsigned smem_u32(const void* p) {
    return (unsigned)__cvta_generic_to_shared(p);
}
__device__ __forceinline__ void mbar_init(unsigned mbar, unsigned cnt) {
    asm volatile("mbarrier.init.shared::cta.b64 [%0], %1;" :: "r"(mbar), "r"(cnt) : "memory");
}
__device__ __forceinline__ void mbar_expect_tx(unsigned mbar, unsigned bytes) {
    asm volatile("mbarrier.arrive.expect_tx.shared::cta.b64 _, [%0], %1;" :: "r"(mbar), "r"(bytes) : "memory");
}
__device__ __forceinline__ void mbar_wait(unsigned mbar, unsigned phase) {
    asm volatile(
        "{\n\t.reg .pred P;\n\t"
        "W_%=:\n\t"
        "mbarrier.try_wait.parity.shared::cta.b64 P, [%0], %1, 0x989680;\n\t"
        "@!P bra W_%=;\n\t}"
        :: "r"(mbar), "r"(phase) : "memory");
}
__device__ __forceinline__ void bulk_g2s(unsigned dst, const void* src, unsigned bytes, unsigned mbar) {
    asm volatile(
        "cp.async.bulk.shared::cta.global.mbarrier::complete_tx::bytes [%0], [%1], %2, [%3];"
        :: "r"(dst), "l"(src), "r"(bytes), "r"(mbar) : "memory");
}

// ---------------------------------------------------------------------------
// Kernel 1: 1x1 conv partials. x tiles staged into SMEM by the bulk-copy
// engine (cp.async.bulk, TMA-class path) instead of per-thread LDG — bypasses
// the per-SM LDG/L1tex request path that capped four LDG variants at ~3.9TB/s.
// g_part[fs][b][j][n] = sum_{f in chunk} x[b,f,n]*w[j,f]
// ---------------------------------------------------------------------------
__global__ __launch_bounds__(TPB1)
void conv_kernel(const float* __restrict__ x, const float* __restrict__ cw)
{
    extern __shared__ __align__(16) unsigned char smem_raw[];
    float2* ws     = (float2*)smem_raw;                          // [FC][J] dup pairs
    float*  stages = (float*)(smem_raw + WS_BYTES);              // [NST][CROWS][WINF]
    unsigned mbar0 = smem_u32(smem_raw + WS_BYTES + NST*STAGE_BYTES);

    const int b   = blockIdx.z;
    const int fs  = blockIdx.y;
    const int f0  = fs * FC;
    const int n0  = blockIdx.x * WINF;
    const int wfl = (NN - n0 < WINF) ? (NN - n0) : WINF;         // floats in window
    const unsigned wbytes = (unsigned)wfl * 4u;
    const int tid = threadIdx.x;

    // Stage weights as (w,w) pairs.
    for (int i = tid; i < FC*J; i += TPB1) {
        int f = i / J, j = i - f*J;
        float w = cw[j*F + f0 + f];
        ws[i] = make_float2(w, w);
    }
    if (tid == 0) {
        #pragma unroll
        for (int s = 0; s < NST; s++) mbar_init(mbar0 + 8*s, 1);
    }
    __syncthreads();

    const float* xbase = x + ((size_t)b*F + f0)*NN + n0;

    // Prologue: fill all NST stages (chunks 0..NST-1).
    if (tid == 0) {
        #pragma unroll
        for (int s = 0; s < NST; s++) {
            mbar_expect_tx(mbar0 + 8*s, wbytes * CROWS);
            unsigned dst = smem_u32(stages + s*CROWS*WINF);
            const float* src = xbase + (size_t)(s*CROWS)*NN;
            #pragma unroll
            for (int u = 0; u < CROWS; u++)
                bulk_g2s(dst + u*WINF*4, src + (size_t)u*NN, wbytes, mbar0 + 8*s);
        }
    }

    unsigned long long acc0[J], acc1[J];
    #pragma unroll
    for (int j = 0; j < J; j++) { acc0[j] = 0ull; acc1[j] = 0ull; }

    const int col = 4*tid;                // this thread's floats within window

    #pragma unroll 1
    for (int c = 0; c < NCHUNK; c++) {
        const int slot = c & (NST-1);
        mbar_wait(mbar0 + 8*slot, (c >> 2) & 1);

        const float* st = stages + slot*CROWS*WINF + col;
        #pragma unroll
        for (int u = 0; u < CROWS; u++) {
            ulonglong2 xv = *(const ulonglong2*)(st + u*WINF);
            const ulonglong2* wp = (const ulonglong2*)&ws[(c*CROWS + u)*J];
            #pragma unroll
            for (int jj = 0; jj < 5; jj++) {
                ulonglong2 w2 = wp[jj];
                FMA2(acc0[2*jj  ], w2.x, xv.x);
                FMA2(acc1[2*jj  ], w2.x, xv.y);
                FMA2(acc0[2*jj+1], w2.y, xv.x);
                FMA2(acc1[2*jj+1], w2.y, xv.y);
            }
        }
        __syncthreads();                  // all consumers done with this stage
        if (tid == 0 && c + NST < NCHUNK) {
            int nc = c + NST;
            mbar_expect_tx(mbar0 + 8*slot, wbytes * CROWS);
            unsigned dst = smem_u32(stages + slot*CROWS*WINF);
            const float* src = xbase + (size_t)(nc*CROWS)*NN;
            #pragma unroll
            for (int u = 0; u < CROWS; u++)
                bulk_g2s(dst + u*WINF*4, src + (size_t)u*NN, wbytes, mbar0 + 8*slot);
        }
    }

    if (col < wfl) {
        float* outp = g_part + (((size_t)fs*B + b)*J)*NN + n0 + col;
        #pragma unroll
        for (int j = 0; j < J; j++) {
            float a, bb, cc, d;
            asm("mov.b64 {%0,%1}, %2;" : "=f"(a), "=f"(bb) : "l"(acc0[j]));
            asm("mov.b64 {%0,%1}, %2;" : "=f"(cc), "=f"(d) : "l"(acc1[j]));
            *(float4*)(outp + (size_t)j*NN) = make_float4(a, bb, cc, d);
        }
    }
}

// ---------------------------------------------------------------------------
// Kernel 2: per-(b,j) top-20 / bottom-20, sort-then-merge, float4 loads.
// ---------------------------------------------------------------------------
#define TPB2 1024
#define GROUPS (NN/4)         // 2500
#define LSTRIDE 14            // sentinel + 12 vals + tail sentinel

__global__ __launch_bounds__(TPB2)
void select_kernel(const float* __restrict__ cb,
                   const float* __restrict__ w1, const float* __restrict__ w2,
                   const float* __restrict__ w3)
{
    __shared__ float s[TPB2*LSTRIDE];
    __shared__ float wt[32][21], wb[32][21];

    const int bj = blockIdx.x, b = bj / J, j = bj - b*J;
    const int tid = threadIdx.x;
    const int lane = tid & 31, wid = tid >> 5;
    const unsigned FULL = 0xffffffffu;

    // Warm L2 with the MLP weights.
    {
        int gid = bj * TPB2 + tid;
        if (gid < (2*R*J)*H1/32) {
            asm volatile("prefetch.global.L2 [%0];" :: "l"(w1 + gid*32));
        } else if (gid < (2*R*J)*H1/32 + H1*H2/32) {
            asm volatile("prefetch.global.L2 [%0];" :: "l"(w2 + (gid - (2*R*J)*H1/32)*32));
        } else if (gid < (2*R*J)*H1/32 + H1*H2/32 + 7) {
            asm volatile("prefetch.global.L2 [%0];" :: "l"(w3 + (gid - (2*R*J)*H1/32 - H1*H2/32)*32));
        }
    }

    float v[12];
    #pragma unroll
    for (int k = 0; k < 12; k++) v[k] = -FLT_MAX;
    int c = 0;
    #pragma unroll
    for (int k = 0; k < 3; k++) {
        int gidx = tid + k*TPB2;
        if (gidx < GROUPS) {
            float4 acc = make_float4(0.f, 0.f, 0.f, 0.f);
            #pragma unroll
            for (int fs = 0; fs < FS; fs++) {
                const float4* p = (const float4*)(g_part + (((size_t)fs*B + b)*J + j)*NN);
                float4 t = p[gidx];
                acc.x += t.x; acc.y += t.y; acc.z += t.z; acc.w += t.w;
            }
            v[4*k+0] = acc.x; v[4*k+1] = acc.y; v[4*k+2] = acc.z; v[4*k+3] = acc.w;
            c += 4;
        }
    }

    // Odd-even transposition sort, descending.
    #pragma unroll
    for (int pass = 0; pass < 12; pass++) {
        #pragma unroll
        for (int i = (pass & 1); i + 1 < 12; i += 2) {
            float hi = fmaxf(v[i], v[i+1]);
            float lo = fminf(v[i], v[i+1]);
            v[i] = hi; v[i+1] = lo;
        }
    }

    float* my = s + tid*LSTRIDE;
    my[0] = FLT_MAX;
    #pragma unroll
    for (int k = 0; k < 12; k++) my[1+k] = v[k];
    my[13] = -FLT_MAX;
    __syncwarp();

    // Phase A: warp-local head/tail merges.
    {
        int mp = 1, np = c;
        float hv = my[1];
        float lv = my[np];
        #pragma unroll 1
        for (int r = 0; r < R; r++) {
            float bv = hv;
            #pragma unroll
            for (int off = 16; off; off >>= 1)
                bv = fmaxf(bv, __shfl_xor_sync(FULL, bv, off));
            unsigned m = __ballot_sync(FULL, hv == bv);
            if (lane == __ffs(m) - 1) { mp++; hv = my[mp]; }
            if (lane == 0) wt[wid][r] = bv;

            float sv = lv;
            #pragma unroll
            for (int off = 16; off; off >>= 1)
                sv = fminf(sv, __shfl_xor_sync(FULL, sv, off));
            unsigned m2 = __ballot_sync(FULL, lv == sv);
            if (lane == __ffs(m2) - 1) { np--; lv = my[np]; }
            if (lane == 0) wb[wid][r] = sv;
        }
        if (lane == 0) { wt[wid][20] = -FLT_MAX; wb[wid][20] = FLT_MAX; }
    }
    __syncthreads();

    // Phase B: two warps merge the 32 warp lists.
    const float bias = cb[j];
    float* out = g_mm + b*(2*R*J) + j*(2*R);

    if (wid == 0) {
        int p = 0; float hv = wt[lane][0];
        #pragma unroll 1
        for (int r = 0; r < R; r++) {
            float bv = hv;
            #pragma unroll
            for (int off = 16; off; off >>= 1)
                bv = fmaxf(bv, __shfl_xor_sync(FULL, bv, off));
            unsigned m = __ballot_sync(FULL, hv == bv);
            if (lane == __ffs(m) - 1) { p++; hv = wt[lane][p]; }
            if (lane == 0) out[r] = bv + bias;
        }
    } else if (wid == 1) {
        int p = 0; float lv = wb[lane][0];
        #pragma unroll 1
        for (int r = 0; r < R; r++) {
            float sv = lv;
            #pragma unroll
            for (int off = 16; off; off >>= 1)
                sv = fminf(sv, __shfl_xor_sync(FULL, sv, off));
            unsigned m = __ballot_sync(FULL, lv == sv);
            if (lane == __ffs(m) - 1) { p++; lv = wb[lane][p]; }
            if (lane == 0) out[2*R - 1 - r] = sv + bias;
        }
    }
}

// ---------------------------------------------------------------------------
// Kernel 3: tiny MLP 400 -> 200 -> 100 -> 2. One block per batch element.
// ---------------------------------------------------------------------------
__global__ __launch_bounds__(256)
void mlp_kernel(const float* __restrict__ w1, const float* __restrict__ b1,
                const float* __restrict__ w2, const float* __restrict__ b2,
                const float* __restrict__ w3, const float* __restrict__ b3,
                float* __restrict__ out)
{
    __shared__ float sin_[2*R*J];
    __shared__ float sh1[H1];
    __shared__ float sh2[H2];
    const int b = blockIdx.x;
    const int tid = threadIdx.x;

    for (int i = tid; i < 2*R*J; i += 256) sin_[i] = g_mm[b*(2*R*J) + i];
    __syncthreads();

    if (tid < H1) {
        float s = b1[tid];
        #pragma unroll 8
        for (int i = 0; i < 2*R*J; i++) s += sin_[i] * w1[i*H1 + tid];
        sh1[tid] = 1.f / (1.f + expf(-s));
    }
    __syncthreads();

    if (tid < H2) {
        float s = b2[tid];
        #pragma unroll 8
        for (int i = 0; i < H1; i++) s += sh1[i] * w2[i*H2 + tid];
        sh2[tid] = 1.f / (1.f + expf(-s));
    }
    __syncthreads();

    if (tid < 64) {
        int k = tid >> 5, lane = tid & 31;
        float s = 0.f;
        #pragma unroll
        for (int i = lane; i < H2; i += 32) s += sh2[i] * w3[i*2 + k];
        #pragma unroll
        for (int off = 16; off; off >>= 1) s += __shfl_down_sync(0xffffffffu, s, off);
        if (lane == 0) out[b*2 + k] = s + b3[k];
    }
}

// ---------------------------------------------------------------------------
extern "C" void kernel_launch(void* const* d_in, const int* in_sizes, int n_in,
                              void* d_out, int out_size)
{
    const float* x  = (const float*)d_in[0];
    const float* cw = (const float*)d_in[1];
    const float* cb = (const float*)d_in[2];
    const float* w1 = (const float*)d_in[3];
    const float* b1 = (const float*)d_in[4];
    const float* w2 = (const float*)d_in[5];
    const float* b2 = (const float*)d_in[6];
    const float* w3 = (const float*)d_in[7];
    const float* b3 = (const float*)d_in[8];
    float* out = (float*)d_out;

    static int smem_set = 0;
    if (!smem_set) {
        cudaFuncSetAttribute(conv_kernel, cudaFuncAttributeMaxDynamicSharedMemorySize, SMEM_CONV);
        smem_set = 1;
    }

    dim3 g1(NBLK1, FS, B);
    conv_kernel<<<g1, TPB1, SMEM_CONV>>>(x, cw);
    select_kernel<<<B*J, TPB2>>>(cb, w1, w2, w3);
    mlp_kernel<<<B, 256>>>(w1, b1, w2, b2, w3, b3, out);
}

// round 7
// speedup vs baseline: 1.7262x; 1.0894x over previous
#include <cuda_runtime.h>
#include <math.h>
#include <float.h>

#define B   8
#define F   2048
#define NN  10000
#define J   10
#define R   20
#define H1  200
#define H2  100

#define FS   8            // F splits
#define FC   (F/FS)       // 256 f-rows per block
#define TPB1 128
#define WINF 512          // floats per n-window (2KB)
#define NBLK1 ((NN + WINF - 1)/WINF)   // 20 (last window = 272 floats)
#define NST  4            // pipeline stages
#define CROWS 4           // f-rows per stage/chunk (8KB stages -> 4 CTAs/SM)
#define NCHUNK (FC/CROWS) // 64

#define WS_BYTES    (FC*J*8)          // float2 dup weights: 20480
#define STAGE_BYTES (CROWS*WINF*4)    // 8192 per stage
#define SMEM_CONV   (WS_BYTES + NST*STAGE_BYTES + 64)   // ~52.3KB -> 4 CTAs/SM

// Scratch (device globals: no allocation allowed)
__device__ float g_part[(size_t)FS*B*J*NN];   // 25.6 MB partial emb sums
__device__ float g_mm[B*2*R*J];               // [8,400] minmax features

#define FMA2(acc, w, xv) asm("fma.rn.f32x2 %0, %1, %2, %0;" : "+l"(acc) : "l"(w), "l"(xv))

__device__ __forceinline__ unsigned smem_u32(const void* p) {
    return (unsigned)__cvta_generic_to_shared(p);
}
__device__ __forceinline__ void mbar_init(unsigned mbar, unsigned cnt) {
    asm volatile("mbarrier.init.shared::cta.b64 [%0], %1;" :: "r"(mbar), "r"(cnt) : "memory");
}
__device__ __forceinline__ void mbar_expect_tx(unsigned mbar, unsigned bytes) {
    asm volatile("mbarrier.arrive.expect_tx.shared::cta.b64 _, [%0], %1;" :: "r"(mbar), "r"(bytes) : "memory");
}
__device__ __forceinline__ void mbar_wait(unsigned mbar, unsigned phase) {
    asm volatile(
        "{\n\t.reg .pred P;\n\t"
        "W_%=:\n\t"
        "mbarrier.try_wait.parity.shared::cta.b64 P, [%0], %1, 0x989680;\n\t"
        "@!P bra W_%=;\n\t}"
        :: "r"(mbar), "r"(phase) : "memory");
}
__device__ __forceinline__ void bulk_g2s(unsigned dst, const void* src, unsigned bytes, unsigned mbar) {
    asm volatile(
        "cp.async.bulk.shared::cta.global.mbarrier::complete_tx::bytes [%0], [%1], %2, [%3];"
        :: "r"(dst), "l"(src), "r"(bytes), "r"(mbar) : "memory");
}

// ---------------------------------------------------------------------------
// Kernel 1: 1x1 conv partials. x tiles staged into SMEM via cp.async.bulk
// (TMA-class engine path). 8KB stages keep SMEM/CTA at 52KB -> 4 CTAs/SM
// (16 warps) so LDS latency and barrier waits overlap across warps.
// g_part[fs][b][j][n] = sum_{f in chunk} x[b,f,n]*w[j,f]
// ---------------------------------------------------------------------------
__global__ __launch_bounds__(TPB1)
void conv_kernel(const float* __restrict__ x, const float* __restrict__ cw)
{
    extern __shared__ __align__(16) unsigned char smem_raw[];
    float2* ws     = (float2*)smem_raw;                          // [FC][J] dup pairs
    float*  stages = (float*)(smem_raw + WS_BYTES);              // [NST][CROWS][WINF]
    unsigned mbar0 = smem_u32(smem_raw + WS_BYTES + NST*STAGE_BYTES);

    const int b   = blockIdx.z;
    const int fs  = blockIdx.y;
    const int f0  = fs * FC;
    const int n0  = blockIdx.x * WINF;
    const int wfl = (NN - n0 < WINF) ? (NN - n0) : WINF;         // floats in window
    const unsigned wbytes = (unsigned)wfl * 4u;
    const int tid = threadIdx.x;

    // Stage weights as (w,w) pairs.
    for (int i = tid; i < FC*J; i += TPB1) {
        int f = i / J, j = i - f*J;
        float w = cw[j*F + f0 + f];
        ws[i] = make_float2(w, w);
    }
    if (tid == 0) {
        #pragma unroll
        for (int s = 0; s < NST; s++) mbar_init(mbar0 + 8*s, 1);
    }
    __syncthreads();

    const float* xbase = x + ((size_t)b*F + f0)*NN + n0;

    // Prologue: fill all NST stages (chunks 0..NST-1).
    if (tid == 0) {
        #pragma unroll
        for (int s = 0; s < NST; s++) {
            mbar_expect_tx(mbar0 + 8*s, wbytes * CROWS);
            unsigned dst = smem_u32(stages + s*CROWS*WINF);
            const float* src = xbase + (size_t)(s*CROWS)*NN;
            #pragma unroll
            for (int u = 0; u < CROWS; u++)
                bulk_g2s(dst + u*WINF*4, src + (size_t)u*NN, wbytes, mbar0 + 8*s);
        }
    }

    unsigned long long acc0[J], acc1[J];
    #pragma unroll
    for (int j = 0; j < J; j++) { acc0[j] = 0ull; acc1[j] = 0ull; }

    const int col = 4*tid;                // this thread's floats within window

    #pragma unroll 1
    for (int c = 0; c < NCHUNK; c++) {
        const int slot = c & (NST-1);
        mbar_wait(mbar0 + 8*slot, (c >> 2) & 1);

        const float* st = stages + slot*CROWS*WINF + col;
        #pragma unroll
        for (int u = 0; u < CROWS; u++) {
            ulonglong2 xv = *(const ulonglong2*)(st + u*WINF);
            const ulonglong2* wp = (const ulonglong2*)&ws[(c*CROWS + u)*J];
            #pragma unroll
            for (int jj = 0; jj < 5; jj++) {
                ulonglong2 w2 = wp[jj];
                FMA2(acc0[2*jj  ], w2.x, xv.x);
                FMA2(acc1[2*jj  ], w2.x, xv.y);
                FMA2(acc0[2*jj+1], w2.y, xv.x);
                FMA2(acc1[2*jj+1], w2.y, xv.y);
            }
        }
        __syncthreads();                  // all consumers done with this stage
        if (tid == 0 && c + NST < NCHUNK) {
            int nc = c + NST;
            mbar_expect_tx(mbar0 + 8*slot, wbytes * CROWS);
            unsigned dst = smem_u32(stages + slot*CROWS*WINF);
            const float* src = xbase + (size_t)(nc*CROWS)*NN;
            #pragma unroll
            for (int u = 0; u < CROWS; u++)
                bulk_g2s(dst + u*WINF*4, src + (size_t)u*NN, wbytes, mbar0 + 8*slot);
        }
    }

    if (col < wfl) {
        float* outp = g_part + (((size_t)fs*B + b)*J)*NN + n0 + col;
        #pragma unroll
        for (int j = 0; j < J; j++) {
            float a, bb, cc, d;
            asm("mov.b64 {%0,%1}, %2;" : "=f"(a), "=f"(bb) : "l"(acc0[j]));
            asm("mov.b64 {%0,%1}, %2;" : "=f"(cc), "=f"(d) : "l"(acc1[j]));
            *(float4*)(outp + (size_t)j*NN) = make_float4(a, bb, cc, d);
        }
    }
}

// ---------------------------------------------------------------------------
// Kernel 2: per-(b,j) top-20 / bottom-20, sort-then-merge, float4 loads.
// ---------------------------------------------------------------------------
#define TPB2 1024
#define GROUPS (NN/4)         // 2500
#define LSTRIDE 14            // sentinel + 12 vals + tail sentinel

__global__ __launch_bounds__(TPB2)
void select_kernel(const float* __restrict__ cb,
                   const float* __restrict__ w1, const float* __restrict__ w2,
                   const float* __restrict__ w3)
{
    __shared__ float s[TPB2*LSTRIDE];
    __shared__ float wt[32][21], wb[32][21];

    const int bj = blockIdx.x, b = bj / J, j = bj - b*J;
    const int tid = threadIdx.x;
    const int lane = tid & 31, wid = tid >> 5;
    const unsigned FULL = 0xffffffffu;

    // Warm L2 with the MLP weights.
    {
        int gid = bj * TPB2 + tid;
        if (gid < (2*R*J)*H1/32) {
            asm volatile("prefetch.global.L2 [%0];" :: "l"(w1 + gid*32));
        } else if (gid < (2*R*J)*H1/32 + H1*H2/32) {
            asm volatile("prefetch.global.L2 [%0];" :: "l"(w2 + (gid - (2*R*J)*H1/32)*32));
        } else if (gid < (2*R*J)*H1/32 + H1*H2/32 + 7) {
            asm volatile("prefetch.global.L2 [%0];" :: "l"(w3 + (gid - (2*R*J)*H1/32 - H1*H2/32)*32));
        }
    }

    float v[12];
    #pragma unroll
    for (int k = 0; k < 12; k++) v[k] = -FLT_MAX;
    int c = 0;
    #pragma unroll
    for (int k = 0; k < 3; k++) {
        int gidx = tid + k*TPB2;
        if (gidx < GROUPS) {
            float4 acc = make_float4(0.f, 0.f, 0.f, 0.f);
            #pragma unroll
            for (int fs = 0; fs < FS; fs++) {
                const float4* p = (const float4*)(g_part + (((size_t)fs*B + b)*J + j)*NN);
                float4 t = p[gidx];
                acc.x += t.x; acc.y += t.y; acc.z += t.z; acc.w += t.w;
            }
            v[4*k+0] = acc.x; v[4*k+1] = acc.y; v[4*k+2] = acc.z; v[4*k+3] = acc.w;
            c += 4;
        }
    }

    // Odd-even transposition sort, descending.
    #pragma unroll
    for (int pass = 0; pass < 12; pass++) {
        #pragma unroll
        for (int i = (pass & 1); i + 1 < 12; i += 2) {
            float hi = fmaxf(v[i], v[i+1]);
            float lo = fminf(v[i], v[i+1]);
            v[i] = hi; v[i+1] = lo;
        }
    }

    float* my = s + tid*LSTRIDE;
    my[0] = FLT_MAX;
    #pragma unroll
    for (int k = 0; k < 12; k++) my[1+k] = v[k];
    my[13] = -FLT_MAX;
    __syncwarp();

    // Phase A: warp-local head/tail merges.
    {
        int mp = 1, np = c;
        float hv = my[1];
        float lv = my[np];
        #pragma unroll 1
        for (int r = 0; r < R; r++) {
            float bv = hv;
            #pragma unroll
            for (int off = 16; off; off >>= 1)
                bv = fmaxf(bv, __shfl_xor_sync(FULL, bv, off));
            unsigned m = __ballot_sync(FULL, hv == bv);
            if (lane == __ffs(m) - 1) { mp++; hv = my[mp]; }
            if (lane == 0) wt[wid][r] = bv;

            float sv = lv;
            #pragma unroll
            for (int off = 16; off; off >>= 1)
                sv = fminf(sv, __shfl_xor_sync(FULL, sv, off));
            unsigned m2 = __ballot_sync(FULL, lv == sv);
            if (lane == __ffs(m2) - 1) { np--; lv = my[np]; }
            if (lane == 0) wb[wid][r] = sv;
        }
        if (lane == 0) { wt[wid][20] = -FLT_MAX; wb[wid][20] = FLT_MAX; }
    }
    __syncthreads();

    // Phase B: two warps merge the 32 warp lists.
    const float bias = cb[j];
    float* out = g_mm + b*(2*R*J) + j*(2*R);

    if (wid == 0) {
        int p = 0; float hv = wt[lane][0];
        #pragma unroll 1
        for (int r = 0; r < R; r++) {
            float bv = hv;
            #pragma unroll
            for (int off = 16; off; off >>= 1)
                bv = fmaxf(bv, __shfl_xor_sync(FULL, bv, off));
            unsigned m = __ballot_sync(FULL, hv == bv);
            if (lane == __ffs(m) - 1) { p++; hv = wt[lane][p]; }
            if (lane == 0) out[r] = bv + bias;
        }
    } else if (wid == 1) {
        int p = 0; float lv = wb[lane][0];
        #pragma unroll 1
        for (int r = 0; r < R; r++) {
            float sv = lv;
            #pragma unroll
            for (int off = 16; off; off >>= 1)
                sv = fminf(sv, __shfl_xor_sync(FULL, sv, off));
            unsigned m = __ballot_sync(FULL, lv == sv);
            if (lane == __ffs(m) - 1) { p++; lv = wb[lane][p]; }
            if (lane == 0) out[2*R - 1 - r] = sv + bias;
        }
    }
}

// ---------------------------------------------------------------------------
// Kernel 3: tiny MLP 400 -> 200 -> 100 -> 2. One block per batch element.
// ---------------------------------------------------------------------------
__global__ __launch_bounds__(256)
void mlp_kernel(const float* __restrict__ w1, const float* __restrict__ b1,
                const float* __restrict__ w2, const float* __restrict__ b2,
                const float* __restrict__ w3, const float* __restrict__ b3,
                float* __restrict__ out)
{
    __shared__ float sin_[2*R*J];
    __shared__ float sh1[H1];
    __shared__ float sh2[H2];
    const int b = blockIdx.x;
    const int tid = threadIdx.x;

    for (int i = tid; i < 2*R*J; i += 256) sin_[i] = g_mm[b*(2*R*J) + i];
    __syncthreads();

    if (tid < H1) {
        float s = b1[tid];
        #pragma unroll 8
        for (int i = 0; i < 2*R*J; i++) s += sin_[i] * w1[i*H1 + tid];
        sh1[tid] = 1.f / (1.f + expf(-s));
    }
    __syncthreads();

    if (tid < H2) {
        float s = b2[tid];
        #pragma unroll 8
        for (int i = 0; i < H1; i++) s += sh1[i] * w2[i*H2 + tid];
        sh2[tid] = 1.f / (1.f + expf(-s));
    }
    __syncthreads();

    if (tid < 64) {
        int k = tid >> 5, lane = tid & 31;
        float s = 0.f;
        #pragma unroll
        for (int i = lane; i < H2; i += 32) s += sh2[i] * w3[i*2 + k];
        #pragma unroll
        for (int off = 16; off; off >>= 1) s += __shfl_down_sync(0xffffffffu, s, off);
        if (lane == 0) out[b*2 + k] = s + b3[k];
    }
}

// ---------------------------------------------------------------------------
extern "C" void kernel_launch(void* const* d_in, const int* in_sizes, int n_in,
                              void* d_out, int out_size)
{
    const float* x  = (const float*)d_in[0];
    const float* cw = (const float*)d_in[1];
    const float* cb = (const float*)d_in[2];
    const float* w1 = (const float*)d_in[3];
    const float* b1 = (const float*)d_in[4];
    const float* w2 = (const float*)d_in[5];
    const float* b2 = (const float*)d_in[6];
    const float* w3 = (const float*)d_in[7];
    const float* b3 = (const float*)d_in[8];
    float* out = (float*)d_out;

    static int smem_set = 0;
    if (!smem_set) {
        cudaFuncSetAttribute(conv_kernel, cudaFuncAttributeMaxDynamicSharedMemorySize, SMEM_CONV);
        smem_set = 1;
    }

    dim3 g1(NBLK1, FS, B);
    conv_kernel<<<g1, TPB1, SMEM_CONV>>>(x, cw);
    select_kernel<<<B*J, TPB2>>>(cb, w1, w2, w3);
    mlp_kernel<<<B, 256>>>(w1, b1, w2, b2, w3, b3, out);
}

// round 8
// speedup vs baseline: 1.7472x; 1.0121x over previous
#include <cuda_runtime.h>
#include <math.h>
#include <float.h>

#define B   8
#define F   2048
#define NN  10000
#define J   10
#define R   20
#define H1  200
#define H2  100

#define FS   8            // F splits
#define FC   (F/FS)       // 256 f-rows per block
#define TPB1 128
#define WINF 512          // floats per n-window (2KB)
#define NBLK1 ((NN + WINF - 1)/WINF)   // 20 (last window = 272 floats)
#define NST  4            // pipeline stages
#define CROWS 2           // f-rows per stage/chunk (4KB stages -> 6 CTAs/SM)
#define NCHUNK (FC/CROWS) // 128

#define WS_BYTES    (FC*J*8)          // float2 dup weights: 20480
#define STAGE_BYTES (CROWS*WINF*4)    // 4096 per stage
#define SMEM_CONV   (WS_BYTES + NST*STAGE_BYTES + 64)   // ~36.6KB -> 6 CTAs/SM

// Scratch (device globals: no allocation allowed)
__device__ float g_part[(size_t)FS*B*J*NN];   // 25.6 MB partial emb sums
__device__ float g_mm[B*2*R*J];               // [8,400] minmax features

#define FMA2(acc, w, xv) asm("fma.rn.f32x2 %0, %1, %2, %0;" : "+l"(acc) : "l"(w), "l"(xv))

__device__ __forceinline__ unsigned smem_u32(const void* p) {
    return (unsigned)__cvta_generic_to_shared(p);
}
__device__ __forceinline__ void mbar_init(unsigned mbar, unsigned cnt) {
    asm volatile("mbarrier.init.shared::cta.b64 [%0], %1;" :: "r"(mbar), "r"(cnt) : "memory");
}
__device__ __forceinline__ void mbar_expect_tx(unsigned mbar, unsigned bytes) {
    asm volatile("mbarrier.arrive.expect_tx.shared::cta.b64 _, [%0], %1;" :: "r"(mbar), "r"(bytes) : "memory");
}
__device__ __forceinline__ void mbar_wait(unsigned mbar, unsigned phase) {
    asm volatile(
        "{\n\t.reg .pred P;\n\t"
        "W_%=:\n\t"
        "mbarrier.try_wait.parity.shared::cta.b64 P, [%0], %1, 0x989680;\n\t"
        "@!P bra W_%=;\n\t}"
        :: "r"(mbar), "r"(phase) : "memory");
}
__device__ __forceinline__ void bulk_g2s(unsigned dst, const void* src, unsigned bytes, unsigned mbar) {
    asm volatile(
        "cp.async.bulk.shared::cta.global.mbarrier::complete_tx::bytes [%0], [%1], %2, [%3];"
        :: "r"(dst), "l"(src), "r"(bytes), "r"(mbar) : "memory");
}

// ---------------------------------------------------------------------------
// Kernel 1: 1x1 conv partials. x tiles staged into SMEM via cp.async.bulk.
// 4KB stages -> 36.6KB SMEM/CTA -> 6 CTAs/SM (24 warps): BW scales with
// resident warps (R6->R7 trend), so +50% warps should push DRAM% toward ~78.
// g_part[fs][b][j][n] = sum_{f in chunk} x[b,f,n]*w[j,f]
// ---------------------------------------------------------------------------
__global__ __launch_bounds__(TPB1, 6)
void conv_kernel(const float* __restrict__ x, const float* __restrict__ cw)
{
    extern __shared__ __align__(16) unsigned char smem_raw[];
    float2* ws     = (float2*)smem_raw;                          // [FC][J] dup pairs
    float*  stages = (float*)(smem_raw + WS_BYTES);              // [NST][CROWS][WINF]
    unsigned mbar0 = smem_u32(smem_raw + WS_BYTES + NST*STAGE_BYTES);

    const int b   = blockIdx.z;
    const int fs  = blockIdx.y;
    const int f0  = fs * FC;
    const int n0  = blockIdx.x * WINF;
    const int wfl = (NN - n0 < WINF) ? (NN - n0) : WINF;         // floats in window
    const unsigned wbytes = (unsigned)wfl * 4u;
    const int tid = threadIdx.x;

    // Stage weights as (w,w) pairs.
    for (int i = tid; i < FC*J; i += TPB1) {
        int f = i / J, j = i - f*J;
        float w = cw[j*F + f0 + f];
        ws[i] = make_float2(w, w);
    }
    if (tid == 0) {
        #pragma unroll
        for (int s = 0; s < NST; s++) mbar_init(mbar0 + 8*s, 1);
    }
    __syncthreads();

    const float* xbase = x + ((size_t)b*F + f0)*NN + n0;

    // Prologue: fill all NST stages (chunks 0..NST-1).
    if (tid == 0) {
        #pragma unroll
        for (int s = 0; s < NST; s++) {
            mbar_expect_tx(mbar0 + 8*s, wbytes * CROWS);
            unsigned dst = smem_u32(stages + s*CROWS*WINF);
            const float* src = xbase + (size_t)(s*CROWS)*NN;
            #pragma unroll
            for (int u = 0; u < CROWS; u++)
                bulk_g2s(dst + u*WINF*4, src + (size_t)u*NN, wbytes, mbar0 + 8*s);
        }
    }

    unsigned long long acc0[J], acc1[J];
    #pragma unroll
    for (int j = 0; j < J; j++) { acc0[j] = 0ull; acc1[j] = 0ull; }

    const int col = 4*tid;                // this thread's floats within window

    #pragma unroll 1
    for (int c = 0; c < NCHUNK; c++) {
        const int slot = c & (NST-1);
        mbar_wait(mbar0 + 8*slot, (c >> 2) & 1);

        const float* st = stages + slot*CROWS*WINF + col;
        #pragma unroll
        for (int u = 0; u < CROWS; u++) {
            ulonglong2 xv = *(const ulonglong2*)(st + u*WINF);
            const ulonglong2* wp = (const ulonglong2*)&ws[(c*CROWS + u)*J];
            #pragma unroll
            for (int jj = 0; jj < 5; jj++) {
                ulonglong2 w2 = wp[jj];
                FMA2(acc0[2*jj  ], w2.x, xv.x);
                FMA2(acc1[2*jj  ], w2.x, xv.y);
                FMA2(acc0[2*jj+1], w2.y, xv.x);
                FMA2(acc1[2*jj+1], w2.y, xv.y);
            }
        }
        __syncthreads();                  // all consumers done with this stage
        if (tid == 0 && c + NST < NCHUNK) {
            int nc = c + NST;
            mbar_expect_tx(mbar0 + 8*slot, wbytes * CROWS);
            unsigned dst = smem_u32(stages + slot*CROWS*WINF);
            const float* src = xbase + (size_t)(nc*CROWS)*NN;
            #pragma unroll
            for (int u = 0; u < CROWS; u++)
                bulk_g2s(dst + u*WINF*4, src + (size_t)u*NN, wbytes, mbar0 + 8*slot);
        }
    }

    if (col < wfl) {
        float* outp = g_part + (((size_t)fs*B + b)*J)*NN + n0 + col;
        #pragma unroll
        for (int j = 0; j < J; j++) {
            float a, bb, cc, d;
            asm("mov.b64 {%0,%1}, %2;" : "=f"(a), "=f"(bb) : "l"(acc0[j]));
            asm("mov.b64 {%0,%1}, %2;" : "=f"(cc), "=f"(d) : "l"(acc1[j]));
            *(float4*)(outp + (size_t)j*NN) = make_float4(a, bb, cc, d);
        }
    }
}

// ---------------------------------------------------------------------------
// Kernel 2: per-(b,j) top-20 / bottom-20, sort-then-merge, float4 loads.
// ---------------------------------------------------------------------------
#define TPB2 1024
#define GROUPS (NN/4)         // 2500
#define LSTRIDE 14            // sentinel + 12 vals + tail sentinel

__global__ __launch_bounds__(TPB2)
void select_kernel(const float* __restrict__ cb,
                   const float* __restrict__ w1, const float* __restrict__ w2,
                   const float* __restrict__ w3)
{
    __shared__ float s[TPB2*LSTRIDE];
    __shared__ float wt[32][21], wb[32][21];

    const int bj = blockIdx.x, b = bj / J, j = bj - b*J;
    const int tid = threadIdx.x;
    const int lane = tid & 31, wid = tid >> 5;
    const unsigned FULL = 0xffffffffu;

    // Warm L2 with the MLP weights.
    {
        int gid = bj * TPB2 + tid;
        if (gid < (2*R*J)*H1/32) {
            asm volatile("prefetch.global.L2 [%0];" :: "l"(w1 + gid*32));
        } else if (gid < (2*R*J)*H1/32 + H1*H2/32) {
            asm volatile("prefetch.global.L2 [%0];" :: "l"(w2 + (gid - (2*R*J)*H1/32)*32));
        } else if (gid < (2*R*J)*H1/32 + H1*H2/32 + 7) {
            asm volatile("prefetch.global.L2 [%0];" :: "l"(w3 + (gid - (2*R*J)*H1/32 - H1*H2/32)*32));
        }
    }

    float v[12];
    #pragma unroll
    for (int k = 0; k < 12; k++) v[k] = -FLT_MAX;
    int c = 0;
    #pragma unroll
    for (int k = 0; k < 3; k++) {
        int gidx = tid + k*TPB2;
        if (gidx < GROUPS) {
            float4 acc = make_float4(0.f, 0.f, 0.f, 0.f);
            #pragma unroll
            for (int fs = 0; fs < FS; fs++) {
                const float4* p = (const float4*)(g_part + (((size_t)fs*B + b)*J + j)*NN);
                float4 t = p[gidx];
                acc.x += t.x; acc.y += t.y; acc.z += t.z; acc.w += t.w;
            }
            v[4*k+0] = acc.x; v[4*k+1] = acc.y; v[4*k+2] = acc.z; v[4*k+3] = acc.w;
            c += 4;
        }
    }

    // Odd-even transposition sort, descending.
    #pragma unroll
    for (int pass = 0; pass < 12; pass++) {
        #pragma unroll
        for (int i = (pass & 1); i + 1 < 12; i += 2) {
            float hi = fmaxf(v[i], v[i+1]);
            float lo = fminf(v[i], v[i+1]);
            v[i] = hi; v[i+1] = lo;
        }
    }

    float* my = s + tid*LSTRIDE;
    my[0] = FLT_MAX;
    #pragma unroll
    for (int k = 0; k < 12; k++) my[1+k] = v[k];
    my[13] = -FLT_MAX;
    __syncwarp();

    // Phase A: warp-local head/tail merges.
    {
        int mp = 1, np = c;
        float hv = my[1];
        float lv = my[np];
        #pragma unroll 1
        for (int r = 0; r < R; r++) {
            float bv = hv;
            #pragma unroll
            for (int off = 16; off; off >>= 1)
                bv = fmaxf(bv, __shfl_xor_sync(FULL, bv, off));
            unsigned m = __ballot_sync(FULL, hv == bv);
            if (lane == __ffs(m) - 1) { mp++; hv = my[mp]; }
            if (lane == 0) wt[wid][r] = bv;

            float sv = lv;
            #pragma unroll
            for (int off = 16; off; off >>= 1)
                sv = fminf(sv, __shfl_xor_sync(FULL, sv, off));
            unsigned m2 = __ballot_sync(FULL, lv == sv);
            if (lane == __ffs(m2) - 1) { np--; lv = my[np]; }
            if (lane == 0) wb[wid][r] = sv;
        }
        if (lane == 0) { wt[wid][20] = -FLT_MAX; wb[wid][20] = FLT_MAX; }
    }
    __syncthreads();

    // Phase B: two warps merge the 32 warp lists.
    const float bias = cb[j];
    float* out = g_mm + b*(2*R*J) + j*(2*R);

    if (wid == 0) {
        int p = 0; float hv = wt[lane][0];
        #pragma unroll 1
        for (int r = 0; r < R; r++) {
            float bv = hv;
            #pragma unroll
            for (int off = 16; off; off >>= 1)
                bv = fmaxf(bv, __shfl_xor_sync(FULL, bv, off));
            unsigned m = __ballot_sync(FULL, hv == bv);
            if (lane == __ffs(m) - 1) { p++; hv = wt[lane][p]; }
            if (lane == 0) out[r] = bv + bias;
        }
    } else if (wid == 1) {
        int p = 0; float lv = wb[lane][0];
        #pragma unroll 1
        for (int r = 0; r < R; r++) {
            float sv = lv;
            #pragma unroll
            for (int off = 16; off; off >>= 1)
                sv = fminf(sv, __shfl_xor_sync(FULL, sv, off));
            unsigned m = __ballot_sync(FULL, lv == sv);
            if (lane == __ffs(m) - 1) { p++; lv = wb[lane][p]; }
            if (lane == 0) out[2*R - 1 - r] = sv + bias;
        }
    }
}

// ---------------------------------------------------------------------------
// Kernel 3: tiny MLP 400 -> 200 -> 100 -> 2. One block per batch element.
// ---------------------------------------------------------------------------
__global__ __launch_bounds__(256)
void mlp_kernel(const float* __restrict__ w1, const float* __restrict__ b1,
                const float* __restrict__ w2, const float* __restrict__ b2,
                const float* __restrict__ w3, const float* __restrict__ b3,
                float* __restrict__ out)
{
    __shared__ float sin_[2*R*J];
    __shared__ float sh1[H1];
    __shared__ float sh2[H2];
    const int b = blockIdx.x;
    const int tid = threadIdx.x;

    for (int i = tid; i < 2*R*J; i += 256) sin_[i] = g_mm[b*(2*R*J) + i];
    __syncthreads();

    if (tid < H1) {
        float s = b1[tid];
        #pragma unroll 8
        for (int i = 0; i < 2*R*J; i++) s += sin_[i] * w1[i*H1 + tid];
        sh1[tid] = 1.f / (1.f + expf(-s));
    }
    __syncthreads();

    if (tid < H2) {
        float s = b2[tid];
        #pragma unroll 8
        for (int i = 0; i < H1; i++) s += sh1[i] * w2[i*H2 + tid];
        sh2[tid] = 1.f / (1.f + expf(-s));
    }
    __syncthreads();

    if (tid < 64) {
        int k = tid >> 5, lane = tid & 31;
        float s = 0.f;
        #pragma unroll
        for (int i = lane; i < H2; i += 32) s += sh2[i] * w3[i*2 + k];
        #pragma unroll
        for (int off = 16; off; off >>= 1) s += __shfl_down_sync(0xffffffffu, s, off);
        if (lane == 0) out[b*2 + k] = s + b3[k];
    }
}

// ---------------------------------------------------------------------------
extern "C" void kernel_launch(void* const* d_in, const int* in_sizes, int n_in,
                              void* d_out, int out_size)
{
    const float* x  = (const float*)d_in[0];
    const float* cw = (const float*)d_in[1];
    const float* cb = (const float*)d_in[2];
    const float* w1 = (const float*)d_in[3];
    const float* b1 = (const float*)d_in[4];
    const float* w2 = (const float*)d_in[5];
    const float* b2 = (const float*)d_in[6];
    const float* w3 = (const float*)d_in[7];
    const float* b3 = (const float*)d_in[8];
    float* out = (float*)d_out;

    static int smem_set = 0;
    if (!smem_set) {
        cudaFuncSetAttribute(conv_kernel, cudaFuncAttributeMaxDynamicSharedMemorySize, SMEM_CONV);
        smem_set = 1;
    }

    dim3 g1(NBLK1, FS, B);
    conv_kernel<<<g1, TPB1, SMEM_CONV>>>(x, cw);
    select_kernel<<<B*J, TPB2>>>(cb, w1, w2, w3);
    mlp_kernel<<<B, 256>>>(w1, b1, w2, b2, w3, b3, out);
}